// round 16
// baseline (speedup 1.0000x reference)
#include <cuda_runtime.h>
#include <cuda_fp16.h>
#include <cstdint>

#define Bn 8192
#define Dn 256
#define INn 64
#define ONn 256

typedef unsigned int u32;
typedef unsigned short u16;

// Fragment-ordered images (uint4 = the 4 .b32 regs one lane feeds to mma):
// A:  [btile32 256][kt 16][mw 2][lane 32]  (a0,a1,a2,a3)
// W1: [chunk 4][kt 16][lane 32]            (b0,b1,b2,b3)
// W2: [chunk 16][j 4][lane 32]             (b0,b1,b2,b3)
__device__ __align__(16) uint4 g_Af[256 * 16 * 2 * 32];   // 4MB
__device__ __align__(16) uint4 g_W1f[4 * 16 * 32];
__device__ __align__(16) uint4 g_W2f[16 * 4 * 32];

__device__ __forceinline__ void mma_f16(float* d, const u32* a, u32 b0, u32 b1) {
    asm volatile("mma.sync.aligned.m16n8k16.row.col.f32.f16.f16.f32 "
                 "{%0,%1,%2,%3}, {%4,%5,%6,%7}, {%8,%9}, {%0,%1,%2,%3};"
                 : "+f"(d[0]), "+f"(d[1]), "+f"(d[2]), "+f"(d[3])
                 : "r"(a[0]), "r"(a[1]), "r"(a[2]), "r"(a[3]), "r"(b0), "r"(b1));
}
__device__ __forceinline__ u16 f2h(float v) {
    return __half_as_ushort(__float2half(v));
}
__device__ __forceinline__ u32 pk(float lo, float hi) {
    return (u32)f2h(lo) | ((u32)f2h(hi) << 16);
}
// octant from 7 register medians (m[i] = tt[8i+7]) — zero memory, 3 selects
__device__ __forceinline__ int octant(const float* m, float x) {
    int o = (m[3] <= x) ? 4 : 0;
    const float t1 = o ? m[5] : m[1];
    o += (t1 <= x) ? 2 : 0;
    const float t2 = (o & 4) ? ((o & 2) ? m[6] : m[4]) : ((o & 2) ? m[2] : m[0]);
    o += (t2 <= x) ? 1 : 0;
    return o;
}
// p = 8*o + parallel count over the octant (2 independent LDS.128)
__device__ __forceinline__ int segidx(const float* tt, const float* m, float x) {
    const int o = octant(m, x) << 3;
    const float4 q0 = *(const float4*)(tt + o);
    const float4 q1 = *(const float4*)(tt + o + 4);
    return o + ((q0.x <= x) ? 1 : 0) + ((q0.y <= x) ? 1 : 0)
             + ((q0.z <= x) ? 1 : 0) + ((q0.w <= x) ? 1 : 0)
             + ((q1.x <= x) ? 1 : 0) + ((q1.y <= x) ? 1 : 0)
             + ((q1.z <= x) ? 1 : 0) + ((q1.w <= x) ? 1 : 0);
}

// ---------------------------------------------------------------------------
// kan_eval: PWL prep + eval, register-median octant search, fragment-order A.
// grid (B/512, D/16), 256 threads, occ 2. bx==0 blocks build W1f/W2f.
// ---------------------------------------------------------------------------
#define R2OFF 3104
#define EVAL_SMEM ((R2OFF + 8320) * 4)

__global__ __launch_bounds__(256, 2) void kan_eval(
    const float* __restrict__ x,
    const float* __restrict__ w1, const float* __restrict__ b1,
    const float* __restrict__ w2, const float* __restrict__ b2,
    const float* __restrict__ wo1, const float* __restrict__ wo2)
{
    extern __shared__ float sm[];
    float*  sT  = sm;                        // [16][64]
    float2* sSC = (float2*)(sm + 1024);      // [16][65]
    float*  r2  = sm + R2OFF;
    float* skey = r2;                        // [16][65]
    float* ssK  = r2 + 3120;
    float* ssS  = r2 + 4160;
    float* ssC  = r2 + 5200;
    float* sx   = r2;                        // [16][520]
    u32*  stgA  = (u32*)r2;                  // [512][9]

    const int t = threadIdx.x;
    const int lane = t & 31, w = t >> 5;
    const int b0 = blockIdx.x << 9;
    const int d0 = blockIdx.y << 4;

    // ---- fragment-ordered weight images (16 bx==0 blocks)
    if (blockIdx.x == 0) {
        const int gid = (blockIdx.y << 8) + t;     // 0..4095
        if (gid < 2048) {
            const int c = gid >> 9, kt = (gid >> 5) & 15, l = gid & 31;
            const int n = (c << 4) + (l >> 2);
            const int k = (kt << 4) + ((l & 3) << 1);
            const float* p0 = wo1 + n * 256 + k;
            const float* p8 = wo1 + (n + 8) * 256 + k;
            g_W1f[gid] = make_uint4(pk(p0[0], p0[1]), pk(p0[8], p0[9]),
                                    pk(p8[0], p8[1]), pk(p8[8], p8[9]));
        } else {
            const int e = gid - 2048;
            const int c = e >> 7, j = (e >> 5) & 3, l = e & 31;
            const int n = (c << 4) + (l >> 2);
            const int k = (j << 4) + ((l & 3) << 1);
            const float* p0 = wo2 + n * 64 + k;
            const float* p8 = wo2 + (n + 8) * 64 + k;
            g_W2f[e] = make_uint4(pk(p0[0], p0[1]), pk(p0[8], p0[9]),
                                  pk(p8[0], p8[1]), pk(p8[8], p8[9]));
        }
    }

    // ---------------- Phase P: LUT build (verified) ----------------
    const int dl = t >> 4;
    const int i0 = (t & 15) << 2;
    float key[4], dS[4], dC[4];
    float myBS = 0.f, myBC = 0.f;
    {
        const int base = (d0 + dl) * INn + i0;
        const float4 w4 = *(const float4*)(w1 + base);
        const float4 b4 = *(const float4*)(b1 + base);
        const float4 v4 = *(const float4*)(w2 + base);
        const float* wf = (const float*)&w4;
        const float* bf = (const float*)&b4;
        const float* vf = (const float*)&v4;
        #pragma unroll
        for (int q = 0; q < 4; ++q) {
            const float ww = wf[q], bb = bf[q], vv = vf[q];
            if (ww == 0.f) {
                key[q] = __int_as_float(0x7f800000);
                dS[q] = 0.f; dC[q] = 0.f;
                myBC += fmaxf(bb, 0.f) * vv;
            } else {
                key[q] = -bb / ww;
                const float pS = ww * vv, pC = bb * vv;
                if (ww > 0.f) { dS[q] = pS;  dC[q] = pC; }
                else          { dS[q] = -pS; dC[q] = -pC; myBS += pS; myBC += pC; }
            }
            skey[dl * 65 + i0 + q] = key[q];
        }
    }
    #pragma unroll
    for (int off = 8; off >= 1; off >>= 1) {
        myBS += __shfl_xor_sync(~0u, myBS, off);
        myBC += __shfl_xor_sync(~0u, myBC, off);
    }
    __syncthreads();

    #pragma unroll
    for (int q = 0; q < 4; ++q) {
        const float kq = key[q];
        const int iq = i0 + q;
        int rank = 0;
        const float* row = skey + dl * 65;
        #pragma unroll
        for (int j = 0; j < 64; ++j) {
            const float tj = row[j];
            rank += (tj < kq || (tj == kq && j < iq)) ? 1 : 0;
        }
        ssK[dl * 65 + rank] = kq;
        ssS[dl * 65 + rank] = dS[q];
        ssC[dl * 65 + rank] = dC[q];
    }
    __syncthreads();

    #pragma unroll
    for (int h = 0; h < 2; ++h) {
        const int dd = (w << 1) + h;
        float s0 = ssS[dd * 65 + lane], s1 = ssS[dd * 65 + lane + 32];
        float c0 = ssC[dd * 65 + lane], c1 = ssC[dd * 65 + lane + 32];
        #pragma unroll
        for (int off = 1; off < 32; off <<= 1) {
            const float a0 = __shfl_up_sync(~0u, s0, off);
            const float a1 = __shfl_up_sync(~0u, c0, off);
            const float a2 = __shfl_up_sync(~0u, s1, off);
            const float a3 = __shfl_up_sync(~0u, c1, off);
            if (lane >= off) { s0 += a0; c0 += a1; s1 += a2; c1 += a3; }
        }
        s1 += __shfl_sync(~0u, s0, 31);
        c1 += __shfl_sync(~0u, c0, 31);
        float bS = __shfl_sync(~0u, myBS, h << 4);
        float bC = __shfl_sync(~0u, myBC, h << 4);
        bC += __ldg(b2 + d0 + dd);
        sT[(dd << 6) + lane]      = ssK[dd * 65 + lane];
        sT[(dd << 6) + lane + 32] = ssK[dd * 65 + lane + 32];
        if (lane == 0) sSC[dd * 65] = make_float2(bS, bC);
        sSC[dd * 65 + 1 + lane]  = make_float2(bS + s0, bC + c0);
        sSC[dd * 65 + 33 + lane] = make_float2(bS + s1, bC + c1);
    }
    __syncthreads();

    // ---------------- Phase E ----------------
    for (int k = t; k < 2048; k += 256) {
        const int b = k >> 2, c4 = (k & 3) << 2;
        const float4 v = *(const float4*)(x + (size_t)(b0 + b) * Dn + d0 + c4);
        sx[(c4 + 0) * 520 + b] = v.x;
        sx[(c4 + 1) * 520 + b] = v.y;
        sx[(c4 + 2) * 520 + b] = v.z;
        sx[(c4 + 3) * 520 + b] = v.w;
    }
    __syncthreads();

    const int dA = w << 1, dB = dA + 1;
    const float*  ttA = sT + (dA << 6);
    const float*  ttB = sT + (dB << 6);
    const float2* scA = sSC + dA * 65;
    const float2* scB = sSC + dB * 65;
    // hoist octile medians (loop-invariant, broadcast LDS)
    float mA[7], mB[7];
    #pragma unroll
    for (int i = 0; i < 7; ++i) {
        mA[i] = ttA[(i << 3) + 7];
        mB[i] = ttB[(i << 3) + 7];
    }
    u32 packA[16];
    #pragma unroll
    for (int ch = 0; ch < 16; ++ch) {
        const int b = (ch << 5) + lane;
        const float xa = sx[dA * 520 + b];
        const float xb = sx[dB * 520 + b];
        const int p = segidx(ttA, mA, xa);
        const int r = segidx(ttB, mB, xb);
        const float2 sa = scA[p];
        const float2 sb2 = scB[r];
        const float va = fmaf(sa.x, xa, sa.y);
        const float vb = fmaf(sb2.x, xb, sb2.y);
        packA[ch] = ((u32)f2h(vb) << 16) | f2h(va);   // low = even d (k)
    }
    __syncthreads();   // sx dead -> staging

    #pragma unroll
    for (int ch = 0; ch < 16; ++ch) {
        const int b = (ch << 5) + lane;
        stgA[b * 9 + w] = packA[ch];
    }
    __syncthreads();

    // ---- fragment-ordered A store (R15-verified)
    for (int idx = t; idx < 1024; idx += 256) {
        const int tt = idx >> 6, mw = (idx >> 5) & 1, l = idx & 31;
        const int gg = l >> 2, tq = l & 3;
        const int bl = (tt << 5) + (mw << 4) + gg;
        const u32 u0 = stgA[bl * 9 + tq];
        const u32 u1 = stgA[(bl + 8) * 9 + tq];
        const u32 u2 = stgA[bl * 9 + tq + 4];
        const u32 u3 = stgA[(bl + 8) * 9 + tq + 4];
        const int bt = (blockIdx.x << 4) + tt;
        g_Af[(((bt << 4) + blockIdx.y) << 6) + (mw << 5) + l] =
            make_uint4(u0, u1, u2, u3);
    }
}

// ---------------------------------------------------------------------------
// kan_mma v6: btile 16, 128 threads (4 n-warps), grid 512, occ up to 6.
// mw lifted into blockIdx (fragment layout unchanged). Same verified math.
// GEMM1: warp = m16 x n16. GEMM2: warp = m16 x n64.
// ---------------------------------------------------------------------------
__global__ __launch_bounds__(128, 6) void kan_mma(
    const float* __restrict__ bo1, const float* __restrict__ bo2,
    float* __restrict__ out)
{
    __shared__ uint4 gfr[4][32];
    __shared__ float sb1[64];
    __shared__ float sb2[256];

    const int t = threadIdx.x;
    const int bt32 = blockIdx.x >> 1;    // 32-row A-image tile
    const int mw = blockIdx.x & 1;       // which m16 half
    const int b0 = blockIdx.x << 4;

    if (t < 64) sb1[t] = __ldg(bo1 + t);
    sb2[t] = __ldg(bo2 + t);
    sb2[t + 128] = __ldg(bo2 + t + 128);
    __syncthreads();

    const int nw = t >> 5, lane = t & 31;
    const int tq = lane & 3, gg = lane >> 2;

    // ---- GEMM1: warp = m16 x n16, K=256
    float D1[2][4] = {};
    const uint4* aP = g_Af + (bt32 << 10) + (mw << 5) + lane;   // + kt*64
    const uint4* bP = g_W1f + (nw << 9) + lane;                 // + kt*32
    #pragma unroll 4
    for (int kt = 0; kt < 16; ++kt) {
        const uint4 av = aP[kt << 6];
        const uint4 bv = bP[kt << 5];
        u32 a[4] = {av.x, av.y, av.z, av.w};
        mma_f16(D1[0], a, bv.x, bv.y);
        mma_f16(D1[1], a, bv.z, bv.w);
    }

    // ---- epilogue 1: relu(D1 + bo1), pack into A2-fragment order
    {
        const int col = (nw << 4) + (tq << 1);
        const float bvA = sb1[col],     bvB = sb1[col + 1];
        const float bvC = sb1[col + 8], bvD = sb1[col + 9];
        const u32 u0 = pk(fmaxf(D1[0][0] + bvA, 0.f), fmaxf(D1[0][1] + bvB, 0.f));
        const u32 u1 = pk(fmaxf(D1[0][2] + bvA, 0.f), fmaxf(D1[0][3] + bvB, 0.f));
        const u32 u2 = pk(fmaxf(D1[1][0] + bvC, 0.f), fmaxf(D1[1][1] + bvD, 0.f));
        const u32 u3 = pk(fmaxf(D1[1][2] + bvC, 0.f), fmaxf(D1[1][3] + bvD, 0.f));
        gfr[nw][lane] = make_uint4(u0, u1, u2, u3);
    }
    __syncthreads();

    // ---- GEMM2: warp = m16 x n64, K=64
    float D2[8][4] = {};
    #pragma unroll
    for (int j = 0; j < 4; ++j) {
        const uint4 ga = gfr[j][lane];
        u32 a2[4] = {ga.x, ga.y, ga.z, ga.w};
        #pragma unroll
        for (int cp = 0; cp < 2; ++cp) {
            const int c0 = (nw << 2) + (cp << 1);
            const uint4 b0v = g_W2f[(((c0 << 2) + j) << 5) + lane];
            const uint4 b1v = g_W2f[((((c0 + 1) << 2) + j) << 5) + lane];
            float* d0 = D2[(cp << 2) + 0];
            float* d1 = D2[(cp << 2) + 1];
            float* d2 = D2[(cp << 2) + 2];
            float* d3 = D2[(cp << 2) + 3];
            mma_f16(d0, a2, b0v.x, b0v.y);
            mma_f16(d1, a2, b0v.z, b0v.w);
            mma_f16(d2, a2, b1v.x, b1v.y);
            mma_f16(d3, a2, b1v.z, b1v.w);
        }
    }

    // ---- store out + bo2
    #pragma unroll
    for (int nt = 0; nt < 8; ++nt) {
        const int ob = (nw << 6) + (nt << 3);
        const float bv0 = sb2[ob + (tq << 1)];
        const float bv1 = sb2[ob + (tq << 1) + 1];
        const int row = b0 + gg;
        *(float2*)(out + (size_t)row * ONn + ob + (tq << 1)) =
            make_float2(D2[nt][0] + bv0, D2[nt][1] + bv1);
        *(float2*)(out + (size_t)(row + 8) * ONn + ob + (tq << 1)) =
            make_float2(D2[nt][2] + bv0, D2[nt][3] + bv1);
    }
}

// ---------------------------------------------------------------------------
extern "C" void kernel_launch(void* const* d_in, const int* in_sizes, int n_in,
                              void* d_out, int out_size)
{
    const float* x   = (const float*)d_in[0];
    const float* w1  = (const float*)d_in[1];
    const float* b1  = (const float*)d_in[2];
    const float* w2  = (const float*)d_in[3];
    const float* b2  = (const float*)d_in[4];
    const float* wo1 = (const float*)d_in[5];
    const float* bo1 = (const float*)d_in[6];
    const float* wo2 = (const float*)d_in[7];
    const float* bo2 = (const float*)d_in[8];
    float* out = (float*)d_out;

    cudaFuncSetAttribute(kan_eval, cudaFuncAttributeMaxDynamicSharedMemorySize, EVAL_SMEM);

    kan_eval<<<dim3(Bn / 512, Dn / 16), 256, EVAL_SMEM>>>(x, w1, b1, w2, b2, wo1, wo2);
    kan_mma<<<Bn / 16, 128>>>(bo1, bo2, out);
}

// round 17
// speedup vs baseline: 1.2003x; 1.2003x over previous
#include <cuda_runtime.h>
#include <cuda_fp16.h>
#include <cstdint>

#define Bn 8192
#define Dn 256
#define INn 64
#define ONn 256

typedef unsigned int u32;
typedef unsigned short u16;

// Fragment-ordered images (uint4 = the 4 .b32 regs one lane feeds to mma):
// A:  [btile32 256][kt 16][mw 2][lane 32]  (a0,a1,a2,a3)
// W1: [chunk 4][kt 16][lane 32]            (b0,b1,b2,b3)
// W2: [chunk 16][j 4][lane 32]             (b0,b1,b2,b3)
__device__ __align__(16) uint4 g_Af[256 * 16 * 2 * 32];   // 4MB
__device__ __align__(16) uint4 g_W1f[4 * 16 * 32];
__device__ __align__(16) uint4 g_W2f[16 * 4 * 32];

__device__ __forceinline__ void mma_f16(float* d, const u32* a, u32 b0, u32 b1) {
    asm volatile("mma.sync.aligned.m16n8k16.row.col.f32.f16.f16.f32 "
                 "{%0,%1,%2,%3}, {%4,%5,%6,%7}, {%8,%9}, {%0,%1,%2,%3};"
                 : "+f"(d[0]), "+f"(d[1]), "+f"(d[2]), "+f"(d[3])
                 : "r"(a[0]), "r"(a[1]), "r"(a[2]), "r"(a[3]), "r"(b0), "r"(b1));
}
__device__ __forceinline__ u16 f2h(float v) {
    return __half_as_ushort(__float2half(v));
}
__device__ __forceinline__ u32 pk(float lo, float hi) {
    return (u32)f2h(lo) | ((u32)f2h(hi) << 16);
}

// ---------------------------------------------------------------------------
// kan_eval v3: grid (B/1024, D/16) = (8,16) = 128 blocks, 512 threads, occ 2.
// Phase P is fully warp-local: warp w owns d-row w (2 keys/lane, interchanged
// float4 rank loop, butterfly base reduce, shfl scan). Phase E: warp w ->
// d-pair (w>>1), b-half (w&1). Fragment-order A store (R15-verified layout).
// ---------------------------------------------------------------------------
#define SXP 1032
#define R2OFF 3104
#define EVAL_SMEM ((R2OFF + 16512) * 4)   // 78464 B

__global__ __launch_bounds__(512, 2) void kan_eval(
    const float* __restrict__ x,
    const float* __restrict__ w1, const float* __restrict__ b1,
    const float* __restrict__ w2, const float* __restrict__ b2,
    const float* __restrict__ wo1, const float* __restrict__ wo2)
{
    extern __shared__ float sm[];
    float*  sT  = sm;                        // [16][64]
    float2* sSC = (float2*)(sm + 1024);      // [16][65]
    float*  r2  = sm + R2OFF;
    // region2 aliases
    float* skey = r2;                        // [16][68] (16B-aligned rows)
    float* ssK  = r2 + 1088;                 // [16][68]
    float* ssS  = r2 + 2176;                 // [16][68]
    float* ssC  = r2 + 3264;                 // [16][68]
    float* sx   = r2;                        // [16][1032]
    u32*  stgA  = (u32*)r2;                  // [1024][9]

    const int t = threadIdx.x;
    const int lane = t & 31, w = t >> 5;     // w = local d-row (0..15)
    const int b0 = blockIdx.x << 10;
    const int d0 = blockIdx.y << 4;

    // ---- fragment-ordered weight images (16 bx==0 blocks, threads 0..255)
    if (blockIdx.x == 0 && t < 256) {
        const int gid = (blockIdx.y << 8) + t;     // 0..4095
        if (gid < 2048) {
            const int c = gid >> 9, kt = (gid >> 5) & 15, l = gid & 31;
            const int n = (c << 4) + (l >> 2);
            const int k = (kt << 4) + ((l & 3) << 1);
            const float* p0 = wo1 + n * 256 + k;
            const float* p8 = wo1 + (n + 8) * 256 + k;
            g_W1f[gid] = make_uint4(pk(p0[0], p0[1]), pk(p0[8], p0[9]),
                                    pk(p8[0], p8[1]), pk(p8[8], p8[9]));
        } else {
            const int e = gid - 2048;
            const int c = e >> 7, j = (e >> 5) & 3, l = e & 31;
            const int n = (c << 4) + (l >> 2);
            const int k = (j << 4) + ((l & 3) << 1);
            const float* p0 = wo2 + n * 64 + k;
            const float* p8 = wo2 + (n + 8) * 64 + k;
            g_W2f[e] = make_uint4(pk(p0[0], p0[1]), pk(p0[8], p0[9]),
                                  pk(p8[0], p8[1]), pk(p8[8], p8[9]));
        }
    }

    // ---------------- Phase P: warp-local LUT build ----------------
    const int i0 = lane << 1;                // this thread's 2 key indices
    float key[2], dS[2], dC[2];
    float myBS = 0.f, myBC = 0.f;
    {
        const int base = (d0 + w) * INn + i0;
        const float2 w2v = *(const float2*)(w1 + base);
        const float2 b2v = *(const float2*)(b1 + base);
        const float2 v2v = *(const float2*)(w2 + base);
        const float wf[2] = {w2v.x, w2v.y};
        const float bf[2] = {b2v.x, b2v.y};
        const float vf[2] = {v2v.x, v2v.y};
        #pragma unroll
        for (int q = 0; q < 2; ++q) {
            const float ww = wf[q], bb = bf[q], vv = vf[q];
            if (ww == 0.f) {
                key[q] = __int_as_float(0x7f800000);
                dS[q] = 0.f; dC[q] = 0.f;
                myBC += fmaxf(bb, 0.f) * vv;
            } else {
                key[q] = -bb / ww;
                const float pS = ww * vv, pC = bb * vv;
                if (ww > 0.f) { dS[q] = pS;  dC[q] = pC; }
                else          { dS[q] = -pS; dC[q] = -pC; myBS += pS; myBC += pC; }
            }
            skey[w * 68 + i0 + q] = key[q];
        }
    }
    __syncwarp();

    // rank loop: interchanged, float4 broadcast loads
    int r0 = 0, r1 = 0;
    {
        const float k0 = key[0], k1 = key[1];
        const float* row = skey + w * 68;
        #pragma unroll
        for (int j = 0; j < 64; j += 4) {
            const float4 tj = *(const float4*)(row + j);
            const float e[4] = {tj.x, tj.y, tj.z, tj.w};
            #pragma unroll
            for (int c = 0; c < 4; ++c) {
                const int jj = j + c;
                r0 += (e[c] < k0 || (e[c] == k0 && jj < i0)) ? 1 : 0;
                r1 += (e[c] < k1 || (e[c] == k1 && jj < i0 + 1)) ? 1 : 0;
            }
        }
    }
    __syncwarp();
    ssK[w * 68 + r0] = key[0]; ssS[w * 68 + r0] = dS[0]; ssC[w * 68 + r0] = dC[0];
    ssK[w * 68 + r1] = key[1]; ssS[w * 68 + r1] = dS[1]; ssC[w * 68 + r1] = dC[1];

    // base reduce (full warp = full row)
    #pragma unroll
    for (int off = 16; off >= 1; off >>= 1) {
        myBS += __shfl_xor_sync(~0u, myBS, off);
        myBC += __shfl_xor_sync(~0u, myBC, off);
    }
    __syncwarp();

    // scan (warp-local, row w)
    {
        float s0 = ssS[w * 68 + lane], s1 = ssS[w * 68 + lane + 32];
        float c0 = ssC[w * 68 + lane], c1 = ssC[w * 68 + lane + 32];
        #pragma unroll
        for (int off = 1; off < 32; off <<= 1) {
            const float a0 = __shfl_up_sync(~0u, s0, off);
            const float a1 = __shfl_up_sync(~0u, c0, off);
            const float a2 = __shfl_up_sync(~0u, s1, off);
            const float a3 = __shfl_up_sync(~0u, c1, off);
            if (lane >= off) { s0 += a0; c0 += a1; s1 += a2; c1 += a3; }
        }
        s1 += __shfl_sync(~0u, s0, 31);
        c1 += __shfl_sync(~0u, c0, 31);
        const float bS = myBS;
        const float bC = myBC + __ldg(b2 + d0 + w);
        sT[(w << 6) + lane]      = ssK[w * 68 + lane];
        sT[(w << 6) + lane + 32] = ssK[w * 68 + lane + 32];
        if (lane == 0) sSC[w * 65] = make_float2(bS, bC);
        sSC[w * 65 + 1 + lane]  = make_float2(bS + s0, bC + c0);
        sSC[w * 65 + 33 + lane] = make_float2(bS + s1, bC + c1);
    }
    __syncthreads();

    // ---------------- Phase E ----------------
    for (int k = t; k < 4096; k += 512) {
        const int b = k >> 2, c4 = (k & 3) << 2;
        const float4 v = *(const float4*)(x + (size_t)(b0 + b) * Dn + d0 + c4);
        sx[(c4 + 0) * SXP + b] = v.x;
        sx[(c4 + 1) * SXP + b] = v.y;
        sx[(c4 + 2) * SXP + b] = v.z;
        sx[(c4 + 3) * SXP + b] = v.w;
    }
    __syncthreads();

    const int pr = w >> 1, h = w & 1;        // d-pair, b-half
    const int dA = pr << 1, dB = dA + 1;
    const float*  ttA = sT + (dA << 6);
    const float*  ttB = sT + (dB << 6);
    const float2* scA = sSC + dA * 65;
    const float2* scB = sSC + dB * 65;
    u32 packA[16];
    #pragma unroll
    for (int ch = 0; ch < 16; ++ch) {
        const int b = (h << 9) + (ch << 5) + lane;
        const float xa = sx[dA * SXP + b];
        const float xb = sx[dB * SXP + b];
        int p = 0;
        p += (ttA[31]     <= xa) ? 32 : 0;
        p += (ttA[p + 15] <= xa) ? 16 : 0;
        p += (ttA[p + 7]  <= xa) ? 8  : 0;
        p += (ttA[p + 3]  <= xa) ? 4  : 0;
        p += (ttA[p + 1]  <= xa) ? 2  : 0;
        p += (ttA[p]      <= xa) ? 1  : 0;
        p += (ttA[p]      <= xa) ? 1  : 0;
        int r = 0;
        r += (ttB[31]     <= xb) ? 32 : 0;
        r += (ttB[r + 15] <= xb) ? 16 : 0;
        r += (ttB[r + 7]  <= xb) ? 8  : 0;
        r += (ttB[r + 3]  <= xb) ? 4  : 0;
        r += (ttB[r + 1]  <= xb) ? 2  : 0;
        r += (ttB[r]      <= xb) ? 1  : 0;
        r += (ttB[r]      <= xb) ? 1  : 0;
        const float2 sa = scA[p];
        const float2 sb2 = scB[r];
        const float va = fmaf(sa.x, xa, sa.y);
        const float vb = fmaf(sb2.x, xb, sb2.y);
        packA[ch] = ((u32)f2h(vb) << 16) | f2h(va);   // low = even d (k)
    }
    __syncthreads();   // all sx reads done -> staging reuse

    #pragma unroll
    for (int ch = 0; ch < 16; ++ch) {
        const int b = (h << 9) + (ch << 5) + lane;
        stgA[b * 9 + pr] = packA[ch];
    }
    __syncthreads();

    // ---- fragment-ordered A store (R15-verified gather, 32 tiles/block)
    for (int idx = t; idx < 2048; idx += 512) {
        const int tt = idx >> 6, mw = (idx >> 5) & 1, l = idx & 31;
        const int gg = l >> 2, tq = l & 3;
        const int bl = (tt << 5) + (mw << 4) + gg;
        const u32 u0 = stgA[bl * 9 + tq];
        const u32 u1 = stgA[(bl + 8) * 9 + tq];
        const u32 u2 = stgA[bl * 9 + tq + 4];
        const u32 u3 = stgA[(bl + 8) * 9 + tq + 4];
        const int bt = (blockIdx.x << 5) + tt;
        g_Af[(((bt << 4) + blockIdx.y) << 6) + (mw << 5) + l] =
            make_uint4(u0, u1, u2, u3);
    }
}

// ---------------------------------------------------------------------------
// kan_mma (R16-verified structure; GEMM1 unroll deepened 4->8, regs for MLP).
// btile 16, 128 threads (4 n-warps), grid 512.
// ---------------------------------------------------------------------------
__global__ __launch_bounds__(128, 4) void kan_mma(
    const float* __restrict__ bo1, const float* __restrict__ bo2,
    float* __restrict__ out)
{
    __shared__ uint4 gfr[4][32];
    __shared__ float sb1[64];
    __shared__ float sb2[256];

    const int t = threadIdx.x;
    const int bt32 = blockIdx.x >> 1;
    const int mw = blockIdx.x & 1;
    const int b0 = blockIdx.x << 4;

    if (t < 64) sb1[t] = __ldg(bo1 + t);
    sb2[t] = __ldg(bo2 + t);
    sb2[t + 128] = __ldg(bo2 + t + 128);
    __syncthreads();

    const int nw = t >> 5, lane = t & 31;
    const int tq = lane & 3, gg = lane >> 2;

    // ---- GEMM1: warp = m16 x n16, K=256, deep unroll for MLP
    float D1[2][4] = {};
    const uint4* aP = g_Af + (bt32 << 10) + (mw << 5) + lane;   // + kt*64
    const uint4* bP = g_W1f + (nw << 9) + lane;                 // + kt*32
    #pragma unroll 8
    for (int kt = 0; kt < 16; ++kt) {
        const uint4 av = aP[kt << 6];
        const uint4 bv = bP[kt << 5];
        u32 a[4] = {av.x, av.y, av.z, av.w};
        mma_f16(D1[0], a, bv.x, bv.y);
        mma_f16(D1[1], a, bv.z, bv.w);
    }

    // ---- epilogue 1: relu(D1 + bo1), pack into A2-fragment order
    {
        const int col = (nw << 4) + (tq << 1);
        const float bvA = sb1[col],     bvB = sb1[col + 1];
        const float bvC = sb1[col + 8], bvD = sb1[col + 9];
        const u32 u0 = pk(fmaxf(D1[0][0] + bvA, 0.f), fmaxf(D1[0][1] + bvB, 0.f));
        const u32 u1 = pk(fmaxf(D1[0][2] + bvA, 0.f), fmaxf(D1[0][3] + bvB, 0.f));
        const u32 u2 = pk(fmaxf(D1[1][0] + bvC, 0.f), fmaxf(D1[1][1] + bvD, 0.f));
        const u32 u3 = pk(fmaxf(D1[1][2] + bvC, 0.f), fmaxf(D1[1][3] + bvD, 0.f));
        gfr[nw][lane] = make_uint4(u0, u1, u2, u3);
    }
    __syncthreads();

    // ---- GEMM2: warp = m16 x n64, K=64
    float D2[8][4] = {};
    #pragma unroll
    for (int j = 0; j < 4; ++j) {
        const uint4 ga = gfr[j][lane];
        u32 a2[4] = {ga.x, ga.y, ga.z, ga.w};
        #pragma unroll
        for (int cp = 0; cp < 2; ++cp) {
            const int c0 = (nw << 2) + (cp << 1);
            const uint4 b0v = g_W2f[(((c0 << 2) + j) << 5) + lane];
            const uint4 b1v = g_W2f[((((c0 + 1) << 2) + j) << 5) + lane];
            float* d0 = D2[(cp << 2) + 0];
            float* d1 = D2[(cp << 2) + 1];
            float* d2 = D2[(cp << 2) + 2];
            float* d3 = D2[(cp << 2) + 3];
            mma_f16(d0, a2, b0v.x, b0v.y);
            mma_f16(d1, a2, b0v.z, b0v.w);
            mma_f16(d2, a2, b1v.x, b1v.y);
            mma_f16(d3, a2, b1v.z, b1v.w);
        }
    }

    // ---- store out + bo2
    #pragma unroll
    for (int nt = 0; nt < 8; ++nt) {
        const int ob = (nw << 6) + (nt << 3);
        const float bv0 = sb2[ob + (tq << 1)];
        const float bv1 = sb2[ob + (tq << 1) + 1];
        const int row = b0 + gg;
        *(float2*)(out + (size_t)row * ONn + ob + (tq << 1)) =
            make_float2(D2[nt][0] + bv0, D2[nt][1] + bv1);
        *(float2*)(out + (size_t)(row + 8) * ONn + ob + (tq << 1)) =
            make_float2(D2[nt][2] + bv0, D2[nt][3] + bv1);
    }
}

// ---------------------------------------------------------------------------
extern "C" void kernel_launch(void* const* d_in, const int* in_sizes, int n_in,
                              void* d_out, int out_size)
{
    const float* x   = (const float*)d_in[0];
    const float* w1  = (const float*)d_in[1];
    const float* b1  = (const float*)d_in[2];
    const float* w2  = (const float*)d_in[3];
    const float* b2  = (const float*)d_in[4];
    const float* wo1 = (const float*)d_in[5];
    const float* bo1 = (const float*)d_in[6];
    const float* wo2 = (const float*)d_in[7];
    const float* bo2 = (const float*)d_in[8];
    float* out = (float*)d_out;

    cudaFuncSetAttribute(kan_eval, cudaFuncAttributeMaxDynamicSharedMemorySize, EVAL_SMEM);

    kan_eval<<<dim3(Bn / 1024, Dn / 16), 512, EVAL_SMEM>>>(x, w1, b1, w2, b2, wo1, wo2);
    kan_mma<<<Bn / 16, 128>>>(bo1, bo2, out);
}